// round 17
// baseline (speedup 1.0000x reference)
#include <cuda_runtime.h>
#include <cuda_fp16.h>
#include <cstdint>
#include <math.h>

#define NTHREADS 512
#define TMC      64
#define NCHUNK   8            // 256 k / 32
#define A_STRIDE 528          // 512 + 16 pad -> ldmatrix conflict-free
#define B_STRIDE 80           // 64 + 16 pad  -> ldmatrix conflict-free
#define A_PLANE  (TMC * A_STRIDE)     // 33792
#define B_MAT    (256 * B_STRIDE)     // 20480 per plane per buf

#define OFF_A1   0
#define OFF_A2   A_PLANE                      // 33792
#define OFF_B    (2 * A_PLANE)                // 67584 ; [2 buf][2 plane]*20480
#define OFF_B2S  (OFF_B + 4 * B_MAT)          // 149504
#define OFF_W3S  (OFF_B2S + 1024)             // 150528
#define OFF_B3S  (OFF_W3S + 3072)             // 153600
#define OFF_RS   (OFF_B3S + 16)               // 153616
#define OFF_W1T  (OFF_RS + 768)               // 154384
#define OFF_B1T  (OFF_W1T + 3072)             // 157456
#define OFF_XS   (OFF_B1T + 1024)             // 158480
#define SMEM_BYTES (OFF_XS + 2304)            // 160784 -> 1 CTA/SM
#define OFF_PSUM OFF_B                        // epilogue reuse (6144 B)

// ---------------- global scratch: W2^T planes, [n][k] 512B rows -------------
// plane1 = fp16(W2); plane2 = fp16(32*W2 - 31*plane1) = Bh/32-compensation
__device__ __align__(128) __half g_w2t_h[256 * 256];
__device__ __align__(128) __half g_w2t_c[256 * 256];

__device__ __forceinline__ uint32_t smem_u32(const void* p) {
    uint32_t a;
    asm("{ .reg .u64 t; cvta.to.shared.u64 t, %1; cvt.u32.u64 %0, t; }" : "=r"(a) : "l"(p));
    return a;
}

#define LDSM4(r, a)                                                           \
    asm volatile("ldmatrix.sync.aligned.m8n8.x4.shared.b16 {%0,%1,%2,%3}, [%4];" \
        : "=r"((r)[0]), "=r"((r)[1]), "=r"((r)[2]), "=r"((r)[3]) : "r"(a))

#define MMA_F16(acc, A, b0, b1)                                               \
    asm volatile(                                                             \
        "mma.sync.aligned.m16n8k16.row.col.f32.f16.f16.f32 "                  \
        "{%0,%1,%2,%3}, {%4,%5,%6,%7}, {%8,%9}, {%0,%1,%2,%3};"               \
        : "+f"((acc)[0]), "+f"((acc)[1]), "+f"((acc)[2]), "+f"((acc)[3])      \
        : "r"((A)[0]), "r"((A)[1]), "r"((A)[2]), "r"((A)[3]),                 \
          "r"(b0), "r"(b1))

#define CP_ASYNC16(dst, src)                                                  \
    asm volatile("cp.async.cg.shared.global [%0], [%1], 16;" :: "r"(dst), "l"(src) : "memory")
#define CP_COMMIT()  asm volatile("cp.async.commit_group;" ::: "memory")
#define CP_WAIT0()   asm volatile("cp.async.wait_group 0;" ::: "memory")

// ---------------- kernel 1: transpose + 2-plane split of W2 ----------------
__global__ void prep_w2(const float* __restrict__ W2) {
    __shared__ float tile[32][33];
    int bx = blockIdx.x & 7;        // n tile
    int by = blockIdx.x >> 3;       // k tile
    int tx = threadIdx.x & 31;
    int ty = threadIdx.x >> 5;
    #pragma unroll
    for (int i = 0; i < 32; i += 8)
        tile[ty + i][tx] = W2[(by * 32 + ty + i) * 256 + bx * 32 + tx];
    __syncthreads();
    #pragma unroll
    for (int i = 0; i < 32; i += 8) {
        int n = bx * 32 + ty + i;
        int k = by * 32 + tx;
        float v = tile[tx][ty + i];                 // W2[k][n]
        __half h = __float2half_rn(v);
        float hf = __half2float(h);
        g_w2t_h[n * 256 + k] = h;
        // Bh + 32*Bl = 32*v - 31*Bh
        g_w2t_c[n * 256 + k] = __float2half_rn(fmaf(32.f, v, -31.f * hf));
    }
}

// issue one B chunk (32 k-cols of both planes) into buffer `buf`
__device__ __forceinline__ void issue_b_chunk(uint32_t sb, int c, int buf, int tid)
{
    const char* gh = (const char*)g_w2t_h;
    const char* gc = (const char*)g_w2t_c;
    #pragma unroll
    for (int u = 0; u < 4; u++) {
        int gi  = u * NTHREADS + tid;     // 0..2047
        int mat = gi >> 10;
        int wi  = gi & 1023;
        int n   = wi >> 2;
        int seg = wi & 3;
        uint32_t dst = sb + OFF_B + (buf * 2 + mat) * B_MAT + n * B_STRIDE + seg * 16;
        CP_ASYNC16(dst, (mat ? gc : gh) + n * 512 + c * 64 + seg * 16);
    }
    CP_COMMIT();
}

// ---------------- kernel 2: fused main ----------------
__global__ __launch_bounds__(NTHREADS, 1)
void nn_adiab_mma(const float* __restrict__ x,
                  const float* __restrict__ W1,
                  const float* __restrict__ b1,
                  const float* __restrict__ b2,
                  const float* __restrict__ W3,
                  const float* __restrict__ b3,
                  float* __restrict__ out,
                  int B)
{
    extern __shared__ __align__(128) char smem[];
    const uint32_t sb = smem_u32(smem);
    const int tid  = threadIdx.x;
    const int wid  = tid >> 5;
    const int lane = tid & 31;
    const int g    = lane >> 2;
    const int t    = lane & 3;
    const int wy   = wid & 1;        // 2 m-warps x 32 rows
    const int wx   = wid >> 1;       // 8 n-warps x 32 cols
    const int m0w  = wy * 32;
    const int n0w  = wx * 32;
    const int row0 = blockIdx.x * TMC;

    // ---- prefetch B chunk 0 into buf 0 ----
    issue_b_chunk(sb, 0, 0, tid);

    float* w1s = (float*)(smem + OFF_W1T);
    float* b1s = (float*)(smem + OFF_B1T);
    float* xs  = (float*)(smem + OFF_XS);
    float* b2s = (float*)(smem + OFF_B2S);
    float* w3s = (float*)(smem + OFF_W3S);
    float* b3s = (float*)(smem + OFF_B3S);
    float* rs  = (float*)(smem + OFF_RS);

    for (int i = tid; i < 768; i += NTHREADS) w1s[i] = W1[i];
    for (int i = tid; i < 256; i += NTHREADS) { b1s[i] = b1[i]; b2s[i] = b2[i]; }
    for (int i = tid; i < 768; i += NTHREADS) w3s[i] = W3[i];
    if (tid < 3) b3s[tid] = b3[tid];
    for (int i = tid; i < TMC * 9; i += NTHREADS) {
        int r = row0 + i / 9;
        xs[i] = (r < B) ? x[(size_t)row0 * 9 + i] : 0.f;
    }
    __syncthreads();

    // ---- pairwise distances ----
    if (tid < TMC) {
        const float* p = xs + tid * 9;
        float ax=p[0],ay=p[1],az=p[2], bx=p[3],by=p[4],bz=p[5], cx=p[6],cy=p[7],cz=p[8];
        float d0x=ax-bx, d0y=ay-by, d0z=az-bz;
        float d1x=ax-cx, d1y=ay-cy, d1z=az-cz;
        float d2x=bx-cx, d2y=by-cy, d2z=bz-cz;
        rs[tid*3+0] = sqrtf(d0x*d0x + d0y*d0y + d0z*d0z);
        rs[tid*3+1] = sqrtf(d1x*d1x + d1y*d1y + d1z*d1z);
        rs[tid*3+2] = sqrtf(d2x*d2x + d2y*d2y + d2z*d2z);
    }
    __syncthreads();

    // ---- build A planes ONCE: A1 = fp16(h1), A2 = fp16(h1 - (31/32)A1) ----
    // 8192 k-pairs, 16 per thread
    #pragma unroll 4
    for (int i = 0; i < 16; i++) {
        int flat = i * NTHREADS + tid;
        int m  = flat >> 7;
        int kp = flat & 127;
        int k  = kp * 2;
        float r0 = rs[m*3+0], r1 = rs[m*3+1], r2 = rs[m*3+2];
        float v0 = fmaf(r0, w1s[k],   fmaf(r1, w1s[256+k],   fmaf(r2, w1s[512+k],   b1s[k])));
        float v1 = fmaf(r0, w1s[k+1], fmaf(r1, w1s[256+k+1], fmaf(r2, w1s[512+k+1], b1s[k+1])));
        v0 = fmaxf(v0, 0.f);
        v1 = fmaxf(v1, 0.f);
        __half2 hp = __floats2half2_rn(v0, v1);
        float h0f = __half2float(__low2half(hp));
        float h1f = __half2float(__high2half(hp));
        // Ah/32 + Al = v - (31/32)*Ah
        __half2 cp2 = __floats2half2_rn(fmaf(-0.96875f, h0f, v0),
                                        fmaf(-0.96875f, h1f, v1));
        uint32_t off = (uint32_t)m * A_STRIDE + (uint32_t)k * 2;
        *(uint32_t*)(smem + OFF_A1 + off) = *(uint32_t*)&hp;
        *(uint32_t*)(smem + OFF_A2 + off) = *(uint32_t*)&cp2;
    }
    __syncthreads();

    // ---- per-thread ldmatrix offsets ----
    const int jj = lane >> 3, rr = lane & 7;
    const int mOff  = ((jj & 1) << 3) + rr;
    const int kOffA = ((jj >> 1) << 3) * 2;          // 0 or 16 B
    const uint32_t aoffA = (uint32_t)(m0w + mOff) * A_STRIDE + kOffA;
    const int nOffB = ((jj >> 1) << 3) + rr;
    const int kOffB = ((jj & 1) << 3) * 2;           // 0 or 16 B
    const uint32_t boffB = (uint32_t)(n0w + nOffB) * B_STRIDE + kOffB;

    // ---- accumulators: acc1 = A1B1, acc2 = A2B2 ----
    float acc1[2][4][4], acc2[2][4][4];
    #pragma unroll
    for (int mt = 0; mt < 2; mt++)
        #pragma unroll
        for (int q = 0; q < 4; q++)
            #pragma unroll
            for (int e = 0; e < 4; e++) { acc1[mt][q][e] = 0.f; acc2[mt][q][e] = 0.f; }

    // ---- mainloop: 8 chunks of k=32, 2-stage B double buffer ----
    for (int c = 0; c < NCHUNK; c++) {
        const int buf = c & 1;
        CP_WAIT0();
        __syncthreads();
        if (c + 1 < NCHUNK)
            issue_b_chunk(sb, c + 1, buf ^ 1, tid);

        #pragma unroll
        for (int kt = 0; kt < 2; kt++) {
            uint32_t a1f[2][4], a2f[2][4];
            const uint32_t ka = aoffA + (uint32_t)(c * 32 + kt * 16) * 2;
            LDSM4(a1f[0], sb + OFF_A1 + ka);
            LDSM4(a1f[1], sb + OFF_A1 + ka + 16 * A_STRIDE);
            LDSM4(a2f[0], sb + OFF_A2 + ka);
            LDSM4(a2f[1], sb + OFF_A2 + ka + 16 * A_STRIDE);

            const uint32_t bb = sb + OFF_B + (buf * 2) * B_MAT + boffB + kt * 32;
            uint32_t bh[8], bc[8];
            LDSM4(bh,     bb);
            LDSM4(bh + 4, bb + 2 * (8 * B_STRIDE));
            LDSM4(bc,     bb + B_MAT);
            LDSM4(bc + 4, bb + B_MAT + 2 * (8 * B_STRIDE));

            #pragma unroll
            for (int mt = 0; mt < 2; mt++)
                #pragma unroll
                for (int q = 0; q < 4; q++)
                    MMA_F16(acc1[mt][q], a1f[mt], bh[2*q], bh[2*q+1]);
            #pragma unroll
            for (int mt = 0; mt < 2; mt++)
                #pragma unroll
                for (int q = 0; q < 4; q++)
                    MMA_F16(acc2[mt][q], a2f[mt], bc[2*q], bc[2*q+1]);
        }
    }

    // ---- epilogue: combine planes + bias2 + relu + layer3 partials ----
    __syncthreads();
    float* psum = (float*)(smem + OFF_PSUM);   // [8 wx][64 row][3]
    #pragma unroll
    for (int mt = 0; mt < 2; mt++) {
        float p[2][3];
        p[0][0]=p[0][1]=p[0][2]=0.f;
        p[1][0]=p[1][1]=p[1][2]=0.f;
        #pragma unroll
        for (int q = 0; q < 4; q++) {
            int n  = n0w + q * 8 + 2 * t;
            int n2 = n + 1;
            float bn = b2s[n], bn2 = b2s[n2];
            // D = (31/32)*acc1 + acc2
            float z00 = fmaf(0.96875f, acc1[mt][q][0], acc2[mt][q][0]);
            float z01 = fmaf(0.96875f, acc1[mt][q][1], acc2[mt][q][1]);
            float z10 = fmaf(0.96875f, acc1[mt][q][2], acc2[mt][q][2]);
            float z11 = fmaf(0.96875f, acc1[mt][q][3], acc2[mt][q][3]);
            float h00 = fmaxf(z00 + bn,  0.f);
            float h01 = fmaxf(z01 + bn2, 0.f);
            float h10 = fmaxf(z10 + bn,  0.f);
            float h11 = fmaxf(z11 + bn2, 0.f);
            #pragma unroll
            for (int j = 0; j < 3; j++) {
                float wA = w3s[n * 3 + j], wB = w3s[n2 * 3 + j];
                p[0][j] = fmaf(h00, wA, fmaf(h01, wB, p[0][j]));
                p[1][j] = fmaf(h10, wA, fmaf(h11, wB, p[1][j]));
            }
        }
        #pragma unroll
        for (int s = 0; s < 2; s++)
            #pragma unroll
            for (int j = 0; j < 3; j++) {
                p[s][j] += __shfl_xor_sync(0xffffffffu, p[s][j], 1);
                p[s][j] += __shfl_xor_sync(0xffffffffu, p[s][j], 2);
            }
        if (t == 0) {
            #pragma unroll
            for (int s = 0; s < 2; s++) {
                int rloc = m0w + mt * 16 + g + 8 * s;
                #pragma unroll
                for (int j = 0; j < 3; j++)
                    psum[(wx * TMC + rloc) * 3 + j] = p[s][j];
            }
        }
    }
    __syncthreads();

    // ---- final cross-warp reduce + eigen + store ----
    if (tid < TMC) {
        int gr = row0 + tid;
        if (gr < B) {
            float w0 = b3s[0], w1 = b3s[1], w2 = b3s[2];
            #pragma unroll
            for (int q = 0; q < 8; q++) {
                w0 += psum[(q * TMC + tid) * 3 + 0];
                w1 += psum[(q * TMC + tid) * 3 + 1];
                w2 += psum[(q * TMC + tid) * 3 + 2];
            }
            float mean = 0.5f * (w0 + w1);
            float dd   = 0.5f * (w0 - w1);
            float rad  = sqrtf(dd * dd + w2 * w2);
            out[(size_t)gr * 2 + 0] = mean - rad;
            out[(size_t)gr * 2 + 1] = mean + rad;
        }
    }
}

extern "C" void kernel_launch(void* const* d_in, const int* in_sizes, int n_in,
                              void* d_out, int out_size)
{
    const float* x  = (const float*)d_in[0];
    const float* W1 = (const float*)d_in[1];
    const float* b1 = (const float*)d_in[2];
    const float* W2 = (const float*)d_in[3];
    const float* b2 = (const float*)d_in[4];
    const float* W3 = (const float*)d_in[5];
    const float* b3 = (const float*)d_in[6];
    float* out = (float*)d_out;

    int B = in_sizes[0] / 9;
    int grid = (B + TMC - 1) / TMC;

    prep_w2<<<64, 256>>>(W2);

    cudaFuncSetAttribute(nn_adiab_mma,
                         cudaFuncAttributeMaxDynamicSharedMemorySize, SMEM_BYTES);
    nn_adiab_mma<<<grid, NTHREADS, SMEM_BYTES>>>(x, W1, b1, b2, W3, b3, out, B);
}